// round 10
// baseline (speedup 1.0000x reference)
#include <cuda_runtime.h>
#include <cuda_fp16.h>
#include <math.h>

#define N_TOK 65536
#define DIM 64
#define KCODE 512
#define IN_DIM 256
#define EPSF 1e-2f

// ---------------- device scratch (16B-aligned) ----------------
__device__ __align__(16) float g_zT[DIM * N_TOK];        // 2*z transposed [d][n]
__device__ __align__(16) float g_A[N_TOK];               // bit-exact ||z||^2
__device__ __align__(16) float g_B[KCODE];               // bit-exact ||e||^2
__device__ __align__(16) float g_eT[DIM * KCODE];        // codebook transposed (exact)
__device__ __align__(16) __half g_ehT[DIM * KCODE];      // codebook transposed (half)
__device__ __align__(16) float g_table[KCODE * IN_DIM];  // cb @ dec_w
__device__ __align__(16) int g_idx[N_TOK];
__device__ __align__(16) unsigned int g_counts[KCODE];
__device__ __align__(16) float g_loss_part[512];

// ---------------- setup: transpose cb (+half copy), counts, B[k] ----------
__global__ void k_setup(const float* __restrict__ cb) {
    int b = blockIdx.x, t = threadIdx.x;
    if (b < 64) {
        float v0 = cb[(size_t)t * DIM + b];
        float v1 = cb[(size_t)(256 + t) * DIM + b];
        g_eT[b * KCODE + t] = v0;
        g_eT[b * KCODE + 256 + t] = v1;
        g_ehT[b * KCODE + t] = __float2half(v0);
        g_ehT[b * KCODE + 256 + t] = __float2half(v1);
    } else {
        int k0 = t, k1 = t + 256;
        g_counts[k0] = 0u; g_counts[k1] = 0u;
        const float* e0 = cb + (size_t)k0 * DIM;
        const float* e1 = cb + (size_t)k1 * DIM;
        float s0 = 0.f, s1 = 0.f;
        for (int d = 0; d < DIM; d++) {
            s0 = __fadd_rn(s0, __fmul_rn(e0[d], e0[d]));
            s1 = __fadd_rn(s1, __fmul_rn(e1[d], e1[d]));
        }
        g_B[k0] = s0; g_B[k1] = s1;
    }
}

// ---------------- table[k][i] = sum_d cb[k][d] * dec_w[d][i] ----------------
__global__ void k_table(const float* __restrict__ cb, const float* __restrict__ dw) {
    __shared__ float e[DIM];
    int k = blockIdx.x, tid = threadIdx.x;
    if (tid < DIM) e[tid] = cb[(size_t)k * DIM + tid];
    __syncthreads();
    float acc = 0.f;
    #pragma unroll 8
    for (int d = 0; d < DIM; d++)
        acc = fmaf(e[d], dw[d * IN_DIM + tid], acc);
    g_table[(size_t)k * IN_DIM + tid] = acc;
}

// ---------------- encoder: z = x @ enc_w (bit-exact chains; R5 form) ------
#define XCH 64
#define XPC 68
__global__ void __launch_bounds__(256, 2)
k_enc(const float* __restrict__ x, const float* __restrict__ w) {
    extern __shared__ float s[];
    float* ws = s;                   // [256][64]
    float* xs = s + IN_DIM * DIM;    // [128][XPC]
    int tid = threadIdx.x;
    size_t rowbase = (size_t)blockIdx.x * 128;

    {
        const float4* wg = (const float4*)w;
        float4* w4 = (float4*)ws;
        #pragma unroll 4
        for (int i = tid; i < IN_DIM * DIM / 4; i += 256) w4[i] = wg[i];
    }

    int rg = tid >> 3, cg = tid & 7;
    float acc[4][8];
    #pragma unroll
    for (int a = 0; a < 4; a++)
        #pragma unroll
        for (int b = 0; b < 8; b++) acc[a][b] = 0.f;

    const float4* xg = (const float4*)(x + rowbase * IN_DIM);

    for (int c = 0; c < 4; c++) {
        __syncthreads();
        #pragma unroll
        for (int it = 0; it < 8; it++) {
            int idx = it * 256 + tid;
            int r = idx >> 4, q = idx & 15;
            *(float4*)(xs + r * XPC + 4 * q) = xg[(size_t)r * 64 + 16 * c + q];
        }
        __syncthreads();

        const float* xr0 = xs + (4 * rg + 0) * XPC;
        const float* xr1 = xs + (4 * rg + 1) * XPC;
        const float* xr2 = xs + (4 * rg + 2) * XPC;
        const float* xr3 = xs + (4 * rg + 3) * XPC;

        #pragma unroll
        for (int i4 = 0; i4 < XCH / 4; i4++) {
            float4 xv0 = *(const float4*)(xr0 + 4 * i4);
            float4 xv1 = *(const float4*)(xr1 + 4 * i4);
            float4 xv2 = *(const float4*)(xr2 + 4 * i4);
            float4 xv3 = *(const float4*)(xr3 + 4 * i4);
            #pragma unroll
            for (int j = 0; j < 4; j++) {
                int i = XCH * c + 4 * i4 + j;
                float4 wa = *(const float4*)(ws + i * DIM + 4 * cg);
                float4 wb = *(const float4*)(ws + i * DIM + 32 + 4 * cg);
                float wv[8] = {wa.x, wa.y, wa.z, wa.w, wb.x, wb.y, wb.z, wb.w};
                float x0 = ((const float*)&xv0)[j];
                float x1 = ((const float*)&xv1)[j];
                float x2 = ((const float*)&xv2)[j];
                float x3 = ((const float*)&xv3)[j];
                #pragma unroll
                for (int b = 0; b < 8; b++) {
                    acc[0][b] = fmaf(x0, wv[b], acc[0][b]);
                    acc[1][b] = fmaf(x1, wv[b], acc[1][b]);
                    acc[2][b] = fmaf(x2, wv[b], acc[2][b]);
                    acc[3][b] = fmaf(x3, wv[b], acc[3][b]);
                }
            }
        }
    }

    #pragma unroll
    for (int b = 0; b < 8; b++) {
        int col = (b < 4) ? (4 * cg + b) : (32 + 4 * cg + (b - 4));
        float4 v;
        v.x = 2.0f * acc[0][b]; v.y = 2.0f * acc[1][b];
        v.z = 2.0f * acc[2][b]; v.w = 2.0f * acc[3][b];
        *(float4*)(g_zT + (size_t)col * N_TOK + rowbase + 4 * rg) = v;
    }

    __syncthreads();
    float* zs = xs;
    #pragma unroll
    for (int a = 0; a < 4; a++)
        #pragma unroll
        for (int b = 0; b < 8; b++) {
            int col = (b < 4) ? (4 * cg + b) : (32 + 4 * cg + (b - 4));
            zs[(4 * rg + a) * 65 + col] = acc[a][b];
        }
    __syncthreads();
    if (tid < 128) {
        const float* zr = zs + tid * 65;
        float sA = 0.f;
        for (int d = 0; d < DIM; d++)
            sA = __fadd_rn(sA, __fmul_rn(zr[d], zr[d]));
        g_A[rowbase + tid] = sA;
    }
}

// ---------------- VQ: HFMA2 filter sweep + exact fp32 recheck -------------
// 512 thr, 128 tokens/block. Sweep: thread (tg=tid>>4, cg=tid&15) owns
// tokens 4tg..+3, codes {256p+16cg .. +15} per pass p in {0,1}; computes
// s_k = B_k - (2z).e_k in half2, stores ALL 512 s per token to smem.
// Scan: thread (token=tid>>2, sub=tid&3) rechecks s<=min+EPS exactly.
__global__ void __launch_bounds__(512, 1) k_vq() {
    extern __shared__ char sm[];
    __half* eh = (__half*)sm;                       // [64][512]   65536B
    __half* sdist = (__half*)(sm + 65536);          // [128][512] 131072B
    unsigned* zp2 = (unsigned*)(sm + 196608);       // [64][128]   32768B
    float* Bs = (float*)(sm + 229376);              // [512]        2048B
    float* As = (float*)(sm + 231424);              // [128]         512B
    int tid = threadIdx.x;
    size_t base = (size_t)blockIdx.x * 128;

    {   // eh: half codebook, linear copy
        const uint4* eg = (const uint4*)g_ehT;
        uint4* e4 = (uint4*)eh;
        #pragma unroll
        for (int i = tid; i < DIM * KCODE / 8; i += 512) e4[i] = eg[i];
        // zp2: packed (2z, 2z) half2 per (d, token)
        #pragma unroll
        for (int it = 0; it < 16; it++) {
            int idx = it * 512 + tid;
            int row = idx >> 7, q = idx & 127;
            float v = g_zT[(size_t)row * N_TOK + base + q];
            __half2 h = __float2half2_rn(v);
            zp2[row * 128 + q] = *(unsigned*)&h;
        }
        if (tid < KCODE) Bs[tid] = g_B[tid];
        if (tid < 128) As[tid] = g_A[base + tid];
    }
    __syncthreads();

    int tg = tid >> 4, cg = tid & 15;
    float rmin[4] = {3.4e38f, 3.4e38f, 3.4e38f, 3.4e38f};

    #pragma unroll
    for (int p = 0; p < 2; p++) {
        __half2 m2[4][8];
        #pragma unroll
        for (int a = 0; a < 4; a++)
            #pragma unroll
            for (int j = 0; j < 8; j++) m2[a][j] = __floats2half2_rn(0.f, 0.f);

        const __half* ebase = eh + 256 * p + 16 * cg;
        const unsigned* zrow = zp2 + 4 * tg;
        #pragma unroll 4
        for (int d = 0; d < DIM; d++) {
            uint4 ea = *(const uint4*)(ebase + d * KCODE);      // codes +0..7
            uint4 eb = *(const uint4*)(ebase + d * KCODE + 8);  // codes +8..15
            const __half2* eap = (const __half2*)&ea;
            const __half2* ebp = (const __half2*)&eb;
            unsigned zu0 = zrow[d * 128 + 0], zu1 = zrow[d * 128 + 1];
            unsigned zu2 = zrow[d * 128 + 2], zu3 = zrow[d * 128 + 3];
            __half2 z2[4] = {*(__half2*)&zu0, *(__half2*)&zu1,
                             *(__half2*)&zu2, *(__half2*)&zu3};
            #pragma unroll
            for (int a = 0; a < 4; a++) {
                m2[a][0] = __hfma2(z2[a], eap[0], m2[a][0]);
                m2[a][1] = __hfma2(z2[a], eap[1], m2[a][1]);
                m2[a][2] = __hfma2(z2[a], eap[2], m2[a][2]);
                m2[a][3] = __hfma2(z2[a], eap[3], m2[a][3]);
                m2[a][4] = __hfma2(z2[a], ebp[0], m2[a][4]);
                m2[a][5] = __hfma2(z2[a], ebp[1], m2[a][5]);
                m2[a][6] = __hfma2(z2[a], ebp[2], m2[a][6]);
                m2[a][7] = __hfma2(z2[a], ebp[3], m2[a][7]);
            }
        }
        // epilogue: s = B - m (fp32), store half, track fp32 min
        #pragma unroll
        for (int a = 0; a < 4; a++) {
            __half2* srow = (__half2*)(sdist + (4 * tg + a) * 512 + 256 * p + 16 * cg);
            #pragma unroll
            for (int j = 0; j < 8; j++) {
                int k = 256 * p + 16 * cg + 2 * j;
                float2 mf = __half22float2(m2[a][j]);
                float s0 = Bs[k] - mf.x;
                float s1 = Bs[k + 1] - mf.y;
                rmin[a] = fminf(rmin[a], fminf(s0, s1));
                srow[j] = __floats2half2_rn(s0, s1);
            }
        }
    }

    // per-token approx min across the 16 cg lanes
    #pragma unroll
    for (int off = 8; off >= 1; off >>= 1) {
        #pragma unroll
        for (int a = 0; a < 4; a++)
            rmin[a] = fminf(rmin[a], __shfl_xor_sync(0xffffffffu, rmin[a], off));
    }
    __syncthreads();                         // sdist complete; zp2 reads done
    float* ths = (float*)zp2;                // reuse zp2 region
    float* lred = (float*)zp2 + 128;
    if (cg == 0) {
        #pragma unroll
        for (int a = 0; a < 4; a++) ths[4 * tg + a] = rmin[a] + EPSF;
    }
    __syncthreads();

    // ---- scan + exact recheck ----
    int token = tid >> 2, sub = tid & 3;
    float th = ths[token];
    float Av = As[token];
    float best = 3.4e38f;
    int bidx = 0;
    const __half2* row = (const __half2*)(sdist + token * 512 + 128 * sub);
    for (int i = 0; i < 64; i++) {
        float2 f = __half22float2(row[i]);
        #pragma unroll
        for (int h = 0; h < 2; h++) {
            float fv = h ? f.y : f.x;
            if (fv <= th) {                           // rare candidate
                int k = 128 * sub + 2 * i + h;
                const float* zp = g_zT + base + token;
                const float* ep = g_eT + k;
                float m = 0.f;                        // bit-exact chain
                #pragma unroll 8
                for (int d = 0; d < DIM; d++)
                    m = fmaf(zp[(size_t)d * N_TOK], ep[d * KCODE], m);
                float de = __fsub_rn(__fadd_rn(Av, Bs[k]), m);
                if (de < best) { best = de; bidx = k; }
            }
        }
    }

    // lex (dist, index) merge across the 4 sub lanes
    #pragma unroll
    for (int off = 2; off >= 1; off >>= 1) {
        float od = __shfl_xor_sync(0xffffffffu, best, off);
        int oi = __shfl_xor_sync(0xffffffffu, bidx, off);
        if (od < best || (od == best && oi < bidx)) { best = od; bidx = oi; }
    }

    float contrib = 0.f;
    if (sub == 0) {
        g_idx[base + token] = bidx;
        atomicAdd(&g_counts[bidx], 1u);
        contrib = best;                       // exact ||z-e||^2 of winner
    }
    #pragma unroll
    for (int off = 16; off >= 1; off >>= 1)
        contrib += __shfl_xor_sync(0xffffffffu, contrib, off);
    int lane = tid & 31;
    if (lane == 0) lred[tid >> 5] = contrib;
    __syncthreads();
    if (tid == 0) {
        float acc = 0.f;
        #pragma unroll
        for (int t = 0; t < 16; t++) acc += lred[t];
        g_loss_part[blockIdx.x] = acc;
    }
}

// ---------------- gather: out[n][i] = table[idx[n]][i] ---------------------
__global__ void k_gather(float* __restrict__ out) {
    __shared__ int sidx[32];
    int tid = threadIdx.x;
    size_t base = (size_t)blockIdx.x * 32;
    if (tid < 32) sidx[tid] = g_idx[base + tid];
    __syncthreads();
    int rr = tid >> 6, q = tid & 63;
    #pragma unroll
    for (int j = 0; j < 8; j++) {
        int t = j * 4 + rr;
        float4 v = *(const float4*)(g_table + (size_t)sidx[t] * IN_DIM + 4 * q);
        float* o = out + (base + t) * IN_DIM + 4 * q;
        o[0] = v.x; o[1] = v.y; o[2] = v.z; o[3] = v.w;
    }
}

// ---------------- final: loss + perplexity ---------------------------------
__global__ void k_final(float* __restrict__ out, int out_size) {
    __shared__ float red[512];
    int tid = threadIdx.x;

    unsigned int cnt = g_counts[tid];
    float p = (float)cnt * (1.0f / (float)N_TOK);
    red[tid] = p * logf(p + 1e-10f);
    __syncthreads();
    for (int st = 256; st > 0; st >>= 1) {
        if (tid < st) red[tid] += red[tid + st];
        __syncthreads();
    }
    float ent = -red[0];
    __syncthreads();

    red[tid] = g_loss_part[tid];
    __syncthreads();
    for (int st = 256; st > 0; st >>= 1) {
        if (tid < st) red[tid] += red[tid + st];
        __syncthreads();
    }
    if (tid == 0) {
        out[0] = 1.25f * red[0] / (float)((size_t)N_TOK * DIM);
        out[out_size - 1] = expf(ent);
    }
}

// ---------------- launch ----------------
extern "C" void kernel_launch(void* const* d_in, const int* in_sizes, int n_in,
                              void* d_out, int out_size) {
    const float* x = nullptr;
    const float* enc_w = nullptr;
    const float* dec_w = nullptr;
    const float* cb = nullptr;
    for (int i = 0; i < n_in; i++) {
        const float* p = (const float*)d_in[i];
        int sz = in_sizes[i];
        if (sz == N_TOK * IN_DIM) x = p;
        else if (sz == KCODE * DIM) cb = p;
        else if (sz == IN_DIM * DIM) { if (!enc_w) enc_w = p; else dec_w = p; }
    }

    const int SM_ENC = (IN_DIM * DIM + 128 * XPC) * 4;   // 100352
    const int SM_VQ  = 231936;                           // see k_vq layout
    cudaFuncSetAttribute(k_enc, cudaFuncAttributeMaxDynamicSharedMemorySize, SM_ENC);
    cudaFuncSetAttribute(k_vq,  cudaFuncAttributeMaxDynamicSharedMemorySize, SM_VQ);

    float* out = (float*)d_out;

    k_setup<<<65, 256>>>(cb);
    k_table<<<512, 256>>>(cb, dec_w);
    k_enc<<<N_TOK / 128, 256, SM_ENC>>>(x, enc_w);
    k_vq<<<N_TOK / 128, 512, SM_VQ>>>();
    k_gather<<<N_TOK / 32, 256>>>(out + 1);
    k_final<<<1, 512>>>(out, out_size);
}

// round 12
// speedup vs baseline: 2.7365x; 2.7365x over previous
#include <cuda_runtime.h>
#include <math.h>

#define N_TOK 65536
#define DIM 64
#define KCODE 512
#define IN_DIM 256

// ---------------- device scratch (16B-aligned) ----------------
__device__ __align__(16) float g_zT[DIM * N_TOK];        // 2*z transposed [d][n]
__device__ __align__(16) float g_A[N_TOK];               // bit-exact ||z||^2
__device__ __align__(16) float g_B[KCODE];               // bit-exact ||e||^2
__device__ __align__(16) float g_eT[DIM * KCODE];        // codebook transposed
__device__ __align__(16) float g_table[KCODE * IN_DIM];  // cb @ dec_w
__device__ __align__(16) int g_idx[N_TOK];
__device__ __align__(16) unsigned int g_counts[KCODE];
__device__ __align__(16) float g_loss_part[512];

// ---------------- setup+table merged --------------------------------------
// grid 512 x 256. Every block k: table row k. Blocks 0..63 also transpose
// row d=blockIdx. Block 64 also does counts + bit-exact norms.
__global__ void k_setup_table(const float* __restrict__ cb,
                              const float* __restrict__ dw) {
    __shared__ float e[DIM];
    int k = blockIdx.x, tid = threadIdx.x;

    if (k < 64) {                        // transpose: eT[d][t] = cb[t][d]
        g_eT[k * KCODE + tid]       = cb[(size_t)tid * DIM + k];
        g_eT[k * KCODE + 256 + tid] = cb[(size_t)(256 + tid) * DIM + k];
    } else if (k == 64) {                // counts + norms (bit-exact chains)
        int k0 = tid, k1 = tid + 256;
        g_counts[k0] = 0u; g_counts[k1] = 0u;
        const float* e0 = cb + (size_t)k0 * DIM;
        const float* e1 = cb + (size_t)k1 * DIM;
        float s0 = 0.f, s1 = 0.f;
        for (int d = 0; d < DIM; d++) {
            s0 = __fadd_rn(s0, __fmul_rn(e0[d], e0[d]));
            s1 = __fadd_rn(s1, __fmul_rn(e1[d], e1[d]));
        }
        g_B[k0] = s0; g_B[k1] = s1;
    }

    // table row k (tolerance-loose)
    if (tid < DIM) e[tid] = cb[(size_t)k * DIM + tid];
    __syncthreads();
    float acc = 0.f;
    #pragma unroll 8
    for (int d = 0; d < DIM; d++)
        acc = fmaf(e[d], dw[d * IN_DIM + tid], acc);
    g_table[(size_t)k * IN_DIM + tid] = acc;
}

// ---------------- encoder: z = x @ enc_w (bit-exact chains; R5 exact) -----
#define XCH 64
#define XPC 68
__global__ void __launch_bounds__(256, 2)
k_enc(const float* __restrict__ x, const float* __restrict__ w) {
    extern __shared__ float s[];
    float* ws = s;                   // [256][64] = 64KB
    float* xs = s + IN_DIM * DIM;    // [128][XPC]
    int tid = threadIdx.x;
    size_t rowbase = (size_t)blockIdx.x * 128;

    {
        const float4* wg = (const float4*)w;
        float4* w4 = (float4*)ws;
        #pragma unroll 4
        for (int i = tid; i < IN_DIM * DIM / 4; i += 256) w4[i] = wg[i];
    }

    int rg = tid >> 3, cg = tid & 7;
    float acc[4][8];
    #pragma unroll
    for (int a = 0; a < 4; a++)
        #pragma unroll
        for (int b = 0; b < 8; b++) acc[a][b] = 0.f;

    const float4* xg = (const float4*)(x + rowbase * IN_DIM);

    for (int c = 0; c < 4; c++) {
        __syncthreads();
        #pragma unroll
        for (int it = 0; it < 8; it++) {
            int idx = it * 256 + tid;
            int r = idx >> 4, q = idx & 15;
            *(float4*)(xs + r * XPC + 4 * q) = xg[(size_t)r * 64 + 16 * c + q];
        }
        __syncthreads();

        const float* xr0 = xs + (4 * rg + 0) * XPC;
        const float* xr1 = xs + (4 * rg + 1) * XPC;
        const float* xr2 = xs + (4 * rg + 2) * XPC;
        const float* xr3 = xs + (4 * rg + 3) * XPC;

        #pragma unroll
        for (int i4 = 0; i4 < XCH / 4; i4++) {
            float4 xv0 = *(const float4*)(xr0 + 4 * i4);
            float4 xv1 = *(const float4*)(xr1 + 4 * i4);
            float4 xv2 = *(const float4*)(xr2 + 4 * i4);
            float4 xv3 = *(const float4*)(xr3 + 4 * i4);
            #pragma unroll
            for (int j = 0; j < 4; j++) {
                int i = XCH * c + 4 * i4 + j;
                float4 wa = *(const float4*)(ws + i * DIM + 4 * cg);
                float4 wb = *(const float4*)(ws + i * DIM + 32 + 4 * cg);
                float wv[8] = {wa.x, wa.y, wa.z, wa.w, wb.x, wb.y, wb.z, wb.w};
                float x0 = ((const float*)&xv0)[j];
                float x1 = ((const float*)&xv1)[j];
                float x2 = ((const float*)&xv2)[j];
                float x3 = ((const float*)&xv3)[j];
                #pragma unroll
                for (int b = 0; b < 8; b++) {
                    acc[0][b] = fmaf(x0, wv[b], acc[0][b]);
                    acc[1][b] = fmaf(x1, wv[b], acc[1][b]);
                    acc[2][b] = fmaf(x2, wv[b], acc[2][b]);
                    acc[3][b] = fmaf(x3, wv[b], acc[3][b]);
                }
            }
        }
    }

    #pragma unroll
    for (int b = 0; b < 8; b++) {
        int col = (b < 4) ? (4 * cg + b) : (32 + 4 * cg + (b - 4));
        float4 v;
        v.x = 2.0f * acc[0][b]; v.y = 2.0f * acc[1][b];
        v.z = 2.0f * acc[2][b]; v.w = 2.0f * acc[3][b];
        *(float4*)(g_zT + (size_t)col * N_TOK + rowbase + 4 * rg) = v;
    }

    __syncthreads();
    float* zs = xs;
    #pragma unroll
    for (int a = 0; a < 4; a++)
        #pragma unroll
        for (int b = 0; b < 8; b++) {
            int col = (b < 4) ? (4 * cg + b) : (32 + 4 * cg + (b - 4));
            zs[(4 * rg + a) * 65 + col] = acc[a][b];
        }
    __syncthreads();
    if (tid < 128) {
        const float* zr = zs + tid * 65;
        float sA = 0.f;
        for (int d = 0; d < DIM; d++)
            sA = __fadd_rn(sA, __fmul_rn(zr[d], zr[d]));
        g_A[rowbase + tid] = sA;
    }
}

// ---------------- VQ (R5 core) + fused gather epilogue --------------------
// 512 thr, 128 tokens/block. Thread (tg=tid>>4 in 0..31, cg=tid&15):
// tokens 4tg..+3; per pass p codes {p*128+4cg+r, p*128+64+4cg+r}, r=0..3.
// Epilogue: out[n][:] = table[idx[n]][:] (coalesced, per-warp 8 tokens).
__global__ void __launch_bounds__(512, 1) k_vq(float* __restrict__ out) {
    extern __shared__ float s[];
    float* eT = s;                       // [64][512] = 131KB
    float* zs = s + DIM * KCODE;         // [64][128] = 32KB  (holds 2*z)
    float* Bs = zs + DIM * 128;          // [512]
    float* As = Bs + KCODE;              // [128]
    float* lred = As + 128;              // [32]
    int* sidx2 = (int*)(lred + 32);      // [128]
    int tid = threadIdx.x;
    size_t base = (size_t)blockIdx.x * 128;

    {   // eT: linear float4 copy
        const float4* eg = (const float4*)g_eT;
        float4* e4 = (float4*)eT;
        #pragma unroll 4
        for (int i = tid; i < DIM * KCODE / 4; i += 512) e4[i] = eg[i];
        // zs[d][tok]: 64 x 32 float4 = 2048 float4
        #pragma unroll
        for (int it = 0; it < 4; it++) {
            int idx = it * 512 + tid;
            int d = idx >> 5, q = idx & 31;
            *(float4*)(zs + d * 128 + 4 * q) =
                *(const float4*)(g_zT + (size_t)d * N_TOK + base + 4 * q);
        }
        if (tid < KCODE) Bs[tid] = g_B[tid];
        if (tid < 128) As[tid] = g_A[base + tid];
    }
    __syncthreads();

    int tg = tid >> 4, cg = tid & 15;
    float best[4];
    int bidx[4];
    #pragma unroll
    for (int t = 0; t < 4; t++) { best[t] = 3.4e38f; bidx[t] = 0; }
    float a0 = As[4 * tg + 0], a1 = As[4 * tg + 1];
    float a2 = As[4 * tg + 2], a3 = As[4 * tg + 3];

    #pragma unroll
    for (int pass = 0; pass < 4; pass++) {
        float m[4][8];
        #pragma unroll
        for (int t = 0; t < 4; t++)
            #pragma unroll
            for (int c = 0; c < 8; c++) m[t][c] = 0.f;

        const float* e1 = eT + pass * 128 + 4 * cg;
        const float* e2 = eT + pass * 128 + 64 + 4 * cg;
        #pragma unroll 4
        for (int d = 0; d < DIM; d++) {
            float4 zf = *(const float4*)(zs + d * 128 + 4 * tg);   // 2*z
            float4 ea = *(const float4*)(e1 + d * KCODE);
            float4 eb = *(const float4*)(e2 + d * KCODE);
            float ev[8] = {ea.x, ea.y, ea.z, ea.w, eb.x, eb.y, eb.z, eb.w};
            #pragma unroll
            for (int c = 0; c < 8; c++) {
                m[0][c] = fmaf(zf.x, ev[c], m[0][c]);
                m[1][c] = fmaf(zf.y, ev[c], m[1][c]);
                m[2][c] = fmaf(zf.z, ev[c], m[2][c]);
                m[3][c] = fmaf(zf.w, ev[c], m[3][c]);
            }
        }
        float av[4] = {a0, a1, a2, a3};
        #pragma unroll
        for (int c = 0; c < 8; c++) {
            int k = pass * 128 + ((c < 4) ? (4 * cg + c) : (64 + 4 * cg + (c - 4)));
            float bk = Bs[k];
            #pragma unroll
            for (int t = 0; t < 4; t++) {
                float dd = __fsub_rn(__fadd_rn(av[t], bk), m[t][c]);
                // within-thread k sequence ascending -> strict < = first index
                if (dd < best[t]) { best[t] = dd; bidx[t] = k; }
            }
        }
    }

    // lexicographic (dist, index) min across the 16 cg lanes (half-warp)
    #pragma unroll
    for (int off = 8; off >= 1; off >>= 1) {
        #pragma unroll
        for (int t = 0; t < 4; t++) {
            float od = __shfl_xor_sync(0xffffffffu, best[t], off);
            int oi = __shfl_xor_sync(0xffffffffu, bidx[t], off);
            if (od < best[t] || (od == best[t] && oi < bidx[t])) {
                best[t] = od; bidx[t] = oi;
            }
        }
    }

    if (cg == 0) {
        float ls = 0.f;
        #pragma unroll
        for (int t = 0; t < 4; t++) {
            size_t n = base + 4 * tg + t;
            g_idx[n] = bidx[t];
            sidx2[4 * tg + t] = bidx[t];
            atomicAdd(&g_counts[bidx[t]], 1u);
            ls += best[t];          // dist == ||z - e||^2 (loose tolerance)
        }
        lred[tg] = ls;
    }
    __syncthreads();
    if (tid == 0) {
        float acc = 0.f;
        #pragma unroll
        for (int t = 0; t < 32; t++) acc += lred[t];
        g_loss_part[blockIdx.x] = acc;
    }

    // ---- fused gather: out[n][i] = table[idx[n]][i] ----
    int w = tid >> 5, lane = tid & 31;
    const float4* tbl4 = (const float4*)g_table;
    #pragma unroll
    for (int t = 0; t < 8; t++) {
        int tok = 8 * w + t;
        const float4* src = tbl4 + (size_t)sidx2[tok] * (IN_DIM / 4);
        float* o = out + (base + tok) * IN_DIM;
        #pragma unroll
        for (int h = 0; h < 2; h++) {
            int c4 = 32 * h + lane;
            float4 v = src[c4];
            float* p = o + 4 * c4;
            p[0] = v.x; p[1] = v.y; p[2] = v.z; p[3] = v.w;
        }
    }
}

// ---------------- final: loss + perplexity ---------------------------------
__global__ void k_final(float* __restrict__ out, int out_size) {
    __shared__ float red[512];
    int tid = threadIdx.x;

    unsigned int cnt = g_counts[tid];
    float p = (float)cnt * (1.0f / (float)N_TOK);
    red[tid] = p * logf(p + 1e-10f);
    __syncthreads();
    for (int st = 256; st > 0; st >>= 1) {
        if (tid < st) red[tid] += red[tid + st];
        __syncthreads();
    }
    float ent = -red[0];
    __syncthreads();

    red[tid] = g_loss_part[tid];
    __syncthreads();
    for (int st = 256; st > 0; st >>= 1) {
        if (tid < st) red[tid] += red[tid + st];
        __syncthreads();
    }
    if (tid == 0) {
        out[0] = 1.25f * red[0] / (float)((size_t)N_TOK * DIM);
        out[out_size - 1] = expf(ent);
    }
}

// ---------------- launch ----------------
extern "C" void kernel_launch(void* const* d_in, const int* in_sizes, int n_in,
                              void* d_out, int out_size) {
    const float* x = nullptr;
    const float* enc_w = nullptr;
    const float* dec_w = nullptr;
    const float* cb = nullptr;
    for (int i = 0; i < n_in; i++) {
        const float* p = (const float*)d_in[i];
        int sz = in_sizes[i];
        if (sz == N_TOK * IN_DIM) x = p;
        else if (sz == KCODE * DIM) cb = p;
        else if (sz == IN_DIM * DIM) { if (!enc_w) enc_w = p; else dec_w = p; }
    }

    const int SM_ENC = (IN_DIM * DIM + 128 * XPC) * 4;                   // 100352
    const int SM_VQ  = (DIM * KCODE + DIM * 128 + KCODE + 128 + 32 + 128) * 4; // 166976
    cudaFuncSetAttribute(k_enc, cudaFuncAttributeMaxDynamicSharedMemorySize, SM_ENC);
    cudaFuncSetAttribute(k_vq,  cudaFuncAttributeMaxDynamicSharedMemorySize, SM_VQ);

    float* out = (float*)d_out;

    k_setup_table<<<512, 256>>>(cb, dec_w);
    k_enc<<<N_TOK / 128, 256, SM_ENC>>>(x, enc_w);
    k_vq<<<N_TOK / 128, 512, SM_VQ>>>(out + 1);
    k_final<<<1, 512>>>(out, out_size);
}

// round 13
// speedup vs baseline: 2.8697x; 1.0487x over previous
#include <cuda_runtime.h>
#include <math.h>

#define N_TOK 65536
#define DIM 64
#define KCODE 512
#define IN_DIM 256

// ---------------- device scratch (16B-aligned) ----------------
__device__ __align__(16) float g_zT[DIM * N_TOK];        // 2*z transposed [d][n]
__device__ __align__(16) float g_A[N_TOK];               // bit-exact ||z||^2
__device__ __align__(16) float g_B[KCODE];               // bit-exact ||e||^2
__device__ __align__(16) float g_eT[DIM * KCODE];        // codebook transposed
__device__ __align__(16) float g_table[KCODE * IN_DIM];  // cb @ dec_w
__device__ __align__(16) int g_idx[N_TOK];
__device__ __align__(16) unsigned int g_counts[KCODE];
__device__ __align__(16) float g_loss_part[512];
__device__ unsigned int g_done;                          // vq completion counter

// ---------------- encoder: z = x @ enc_w (bit-exact chains; R5 core) ------
// + fused setup: every block writes table row blockIdx; blocks 0..63 also
//   transpose eT row; block 64 does counts+norms; block 65 resets g_done.
#define XCH 64
#define XPC 68
__global__ void __launch_bounds__(256, 2)
k_enc(const float* __restrict__ x, const float* __restrict__ w,
      const float* __restrict__ cb, const float* __restrict__ dw) {
    extern __shared__ float s[];
    float* ws = s;                   // [256][64] = 64KB
    float* xs = s + IN_DIM * DIM;    // [128][XPC]
    int tid = threadIdx.x;
    int blk = blockIdx.x;
    size_t rowbase = (size_t)blk * 128;

    {
        const float4* wg = (const float4*)w;
        float4* w4 = (float4*)ws;
        #pragma unroll 4
        for (int i = tid; i < IN_DIM * DIM / 4; i += 256) w4[i] = wg[i];
    }

    int rg = tid >> 3, cg = tid & 7;
    float acc[4][8];
    #pragma unroll
    for (int a = 0; a < 4; a++)
        #pragma unroll
        for (int b = 0; b < 8; b++) acc[a][b] = 0.f;

    const float4* xg = (const float4*)(x + rowbase * IN_DIM);

    for (int c = 0; c < 4; c++) {
        __syncthreads();
        #pragma unroll
        for (int it = 0; it < 8; it++) {
            int idx = it * 256 + tid;
            int r = idx >> 4, q = idx & 15;
            *(float4*)(xs + r * XPC + 4 * q) = xg[(size_t)r * 64 + 16 * c + q];
        }
        __syncthreads();

        const float* xr0 = xs + (4 * rg + 0) * XPC;
        const float* xr1 = xs + (4 * rg + 1) * XPC;
        const float* xr2 = xs + (4 * rg + 2) * XPC;
        const float* xr3 = xs + (4 * rg + 3) * XPC;

        #pragma unroll
        for (int i4 = 0; i4 < XCH / 4; i4++) {
            float4 xv0 = *(const float4*)(xr0 + 4 * i4);
            float4 xv1 = *(const float4*)(xr1 + 4 * i4);
            float4 xv2 = *(const float4*)(xr2 + 4 * i4);
            float4 xv3 = *(const float4*)(xr3 + 4 * i4);
            #pragma unroll
            for (int j = 0; j < 4; j++) {
                int i = XCH * c + 4 * i4 + j;
                float4 wa = *(const float4*)(ws + i * DIM + 4 * cg);
                float4 wb = *(const float4*)(ws + i * DIM + 32 + 4 * cg);
                float wv[8] = {wa.x, wa.y, wa.z, wa.w, wb.x, wb.y, wb.z, wb.w};
                float x0 = ((const float*)&xv0)[j];
                float x1 = ((const float*)&xv1)[j];
                float x2 = ((const float*)&xv2)[j];
                float x3 = ((const float*)&xv3)[j];
                #pragma unroll
                for (int b = 0; b < 8; b++) {
                    acc[0][b] = fmaf(x0, wv[b], acc[0][b]);
                    acc[1][b] = fmaf(x1, wv[b], acc[1][b]);
                    acc[2][b] = fmaf(x2, wv[b], acc[2][b]);
                    acc[3][b] = fmaf(x3, wv[b], acc[3][b]);
                }
            }
        }
    }

    #pragma unroll
    for (int b = 0; b < 8; b++) {
        int col = (b < 4) ? (4 * cg + b) : (32 + 4 * cg + (b - 4));
        float4 v;
        v.x = 2.0f * acc[0][b]; v.y = 2.0f * acc[1][b];
        v.z = 2.0f * acc[2][b]; v.w = 2.0f * acc[3][b];
        *(float4*)(g_zT + (size_t)col * N_TOK + rowbase + 4 * rg) = v;
    }

    __syncthreads();
    float* zs = xs;
    #pragma unroll
    for (int a = 0; a < 4; a++)
        #pragma unroll
        for (int b = 0; b < 8; b++) {
            int col = (b < 4) ? (4 * cg + b) : (32 + 4 * cg + (b - 4));
            zs[(4 * rg + a) * 65 + col] = acc[a][b];
        }
    __syncthreads();
    if (tid < 128) {
        const float* zr = zs + tid * 65;
        float sA = 0.f;
        for (int d = 0; d < DIM; d++)
            sA = __fadd_rn(sA, __fmul_rn(zr[d], zr[d]));
        g_A[rowbase + tid] = sA;
    }

    // ---- fused setup (runs once per block; k_vq launches after k_enc) ----
    __syncthreads();
    float* esh = s;                       // reuse smem
    if (tid < DIM) esh[tid] = cb[(size_t)blk * DIM + tid];
    __syncthreads();
    {   // table row blk
        float accT = 0.f;
        #pragma unroll 8
        for (int d = 0; d < DIM; d++)
            accT = fmaf(esh[d], dw[d * IN_DIM + tid], accT);
        g_table[(size_t)blk * IN_DIM + tid] = accT;
    }
    if (blk < 64) {                       // transpose: eT[blk][t] = cb[t][blk]
        g_eT[blk * KCODE + tid]       = cb[(size_t)tid * DIM + blk];
        g_eT[blk * KCODE + 256 + tid] = cb[(size_t)(256 + tid) * DIM + blk];
    } else if (blk == 64) {               // counts + bit-exact norms
        int k0 = tid, k1 = tid + 256;
        g_counts[k0] = 0u; g_counts[k1] = 0u;
        const float* e0 = cb + (size_t)k0 * DIM;
        const float* e1 = cb + (size_t)k1 * DIM;
        float s0 = 0.f, s1 = 0.f;
        for (int d = 0; d < DIM; d++) {
            s0 = __fadd_rn(s0, __fmul_rn(e0[d], e0[d]));
            s1 = __fadd_rn(s1, __fmul_rn(e1[d], e1[d]));
        }
        g_B[k0] = s0; g_B[k1] = s1;
    } else if (blk == 65 && tid == 0) {
        g_done = 0u;                      // reset completion counter
    }
}

// ---------------- VQ (R5 core) + gather + last-block final ----------------
// 512 thr, 128 tokens/block. Thread (tg=tid>>4, cg=tid&15): tokens 4tg..+3;
// per pass p codes {p*128+4cg+r, p*128+64+4cg+r}. Gather + final fused.
__global__ void __launch_bounds__(512, 1) k_vq(float* __restrict__ out,
                                               int out_size) {
    extern __shared__ float s[];
    float* eT = s;                       // [64][512] = 131KB
    float* zs = s + DIM * KCODE;         // [64][128] = 32KB  (holds 2*z)
    float* Bs = zs + DIM * 128;          // [512]
    float* As = Bs + KCODE;              // [128]
    float* lred = As + 128;              // [32]
    int* sidx2 = (int*)(lred + 32);      // [128]
    int tid = threadIdx.x;
    size_t base = (size_t)blockIdx.x * 128;

    {   // eT: linear float4 copy
        const float4* eg = (const float4*)g_eT;
        float4* e4 = (float4*)eT;
        #pragma unroll 4
        for (int i = tid; i < DIM * KCODE / 4; i += 512) e4[i] = eg[i];
        #pragma unroll
        for (int it = 0; it < 4; it++) {
            int idx = it * 512 + tid;
            int d = idx >> 5, q = idx & 31;
            *(float4*)(zs + d * 128 + 4 * q) =
                *(const float4*)(g_zT + (size_t)d * N_TOK + base + 4 * q);
        }
        if (tid < KCODE) Bs[tid] = g_B[tid];
        if (tid < 128) As[tid] = g_A[base + tid];
    }
    __syncthreads();

    int tg = tid >> 4, cg = tid & 15;
    float best[4];
    int bidx[4];
    #pragma unroll
    for (int t = 0; t < 4; t++) { best[t] = 3.4e38f; bidx[t] = 0; }
    float a0 = As[4 * tg + 0], a1 = As[4 * tg + 1];
    float a2 = As[4 * tg + 2], a3 = As[4 * tg + 3];

    #pragma unroll
    for (int pass = 0; pass < 4; pass++) {
        float m[4][8];
        #pragma unroll
        for (int t = 0; t < 4; t++)
            #pragma unroll
            for (int c = 0; c < 8; c++) m[t][c] = 0.f;

        const float* e1 = eT + pass * 128 + 4 * cg;
        const float* e2 = eT + pass * 128 + 64 + 4 * cg;
        #pragma unroll 4
        for (int d = 0; d < DIM; d++) {
            float4 zf = *(const float4*)(zs + d * 128 + 4 * tg);   // 2*z
            float4 ea = *(const float4*)(e1 + d * KCODE);
            float4 eb = *(const float4*)(e2 + d * KCODE);
            float ev[8] = {ea.x, ea.y, ea.z, ea.w, eb.x, eb.y, eb.z, eb.w};
            #pragma unroll
            for (int c = 0; c < 8; c++) {
                m[0][c] = fmaf(zf.x, ev[c], m[0][c]);
                m[1][c] = fmaf(zf.y, ev[c], m[1][c]);
                m[2][c] = fmaf(zf.z, ev[c], m[2][c]);
                m[3][c] = fmaf(zf.w, ev[c], m[3][c]);
            }
        }
        float av[4] = {a0, a1, a2, a3};
        #pragma unroll
        for (int c = 0; c < 8; c++) {
            int k = pass * 128 + ((c < 4) ? (4 * cg + c) : (64 + 4 * cg + (c - 4)));
            float bk = Bs[k];
            #pragma unroll
            for (int t = 0; t < 4; t++) {
                float dd = __fsub_rn(__fadd_rn(av[t], bk), m[t][c]);
                // within-thread k ascending -> strict < = first occurrence
                if (dd < best[t]) { best[t] = dd; bidx[t] = k; }
            }
        }
    }

    // lexicographic (dist, index) min across the 16 cg lanes
    #pragma unroll
    for (int off = 8; off >= 1; off >>= 1) {
        #pragma unroll
        for (int t = 0; t < 4; t++) {
            float od = __shfl_xor_sync(0xffffffffu, best[t], off);
            int oi = __shfl_xor_sync(0xffffffffu, bidx[t], off);
            if (od < best[t] || (od == best[t] && oi < bidx[t])) {
                best[t] = od; bidx[t] = oi;
            }
        }
    }

    if (cg == 0) {
        float ls = 0.f;
        #pragma unroll
        for (int t = 0; t < 4; t++) {
            size_t n = base + 4 * tg + t;
            g_idx[n] = bidx[t];
            sidx2[4 * tg + t] = bidx[t];
            atomicAdd(&g_counts[bidx[t]], 1u);
            ls += best[t];          // dist == ||z - e||^2 (loose tolerance)
        }
        lred[tg] = ls;
    }
    __syncthreads();
    if (tid == 0) {
        float acc = 0.f;
        #pragma unroll
        for (int t = 0; t < 32; t++) acc += lred[t];
        g_loss_part[blockIdx.x] = acc;
    }

    // ---- fused gather: out[n][i] = table[idx[n]][i] ----
    float* og = out + 1;
    int w = tid >> 5, lane = tid & 31;
    const float4* tbl4 = (const float4*)g_table;
    #pragma unroll
    for (int t = 0; t < 8; t++) {
        int tok = 8 * w + t;
        const float4* src = tbl4 + (size_t)sidx2[tok] * (IN_DIM / 4);
        float* o = og + (base + tok) * IN_DIM;
        #pragma unroll
        for (int h = 0; h < 2; h++) {
            int c4 = 32 * h + lane;
            float4 v = src[c4];
            float* p = o + 4 * c4;
            p[0] = v.x; p[1] = v.y; p[2] = v.z; p[3] = v.w;
        }
    }

    // ---- last-block final: loss + perplexity ----
    __threadfence();
    __shared__ unsigned int isLast;
    if (tid == 0) isLast = (atomicAdd(&g_done, 1u) == (unsigned)(gridDim.x - 1));
    __syncthreads();
    if (isLast) {
        float* red = s;                   // reuse smem
        unsigned int cnt = g_counts[tid];
        float p = (float)cnt * (1.0f / (float)N_TOK);
        red[tid] = p * logf(p + 1e-10f);
        __syncthreads();
        for (int st = 256; st > 0; st >>= 1) {
            if (tid < st) red[tid] += red[tid + st];
            __syncthreads();
        }
        float ent = -red[0];
        __syncthreads();

        red[tid] = g_loss_part[tid];
        __syncthreads();
        for (int st = 256; st > 0; st >>= 1) {
            if (tid < st) red[tid] += red[tid + st];
            __syncthreads();
        }
        if (tid == 0) {
            out[0] = 1.25f * red[0] / (float)((size_t)N_TOK * DIM);
            out[out_size - 1] = expf(ent);
        }
    }
}

// ---------------- launch ----------------
extern "C" void kernel_launch(void* const* d_in, const int* in_sizes, int n_in,
                              void* d_out, int out_size) {
    const float* x = nullptr;
    const float* enc_w = nullptr;
    const float* dec_w = nullptr;
    const float* cb = nullptr;
    for (int i = 0; i < n_in; i++) {
        const float* p = (const float*)d_in[i];
        int sz = in_sizes[i];
        if (sz == N_TOK * IN_DIM) x = p;
        else if (sz == KCODE * DIM) cb = p;
        else if (sz == IN_DIM * DIM) { if (!enc_w) enc_w = p; else dec_w = p; }
    }

    const int SM_ENC = (IN_DIM * DIM + 128 * XPC) * 4;                         // 100352
    const int SM_VQ  = (DIM * KCODE + DIM * 128 + KCODE + 128 + 32 + 128) * 4; // 166976
    cudaFuncSetAttribute(k_enc, cudaFuncAttributeMaxDynamicSharedMemorySize, SM_ENC);
    cudaFuncSetAttribute(k_vq,  cudaFuncAttributeMaxDynamicSharedMemorySize, SM_VQ);

    float* out = (float*)d_out;

    k_enc<<<N_TOK / 128, 256, SM_ENC>>>(x, enc_w, cb, dec_w);
    k_vq<<<N_TOK / 128, 512, SM_VQ>>>(out, out_size);
}